// round 8
// baseline (speedup 1.0000x reference)
#include <cuda_runtime.h>
#include <cuda_bf16.h>
#include <cuda_fp8.h>
#include <cstdint>

#define BATCH 16384
#define EMBED 256
#define NS    4096
#define VOCAB 50000

// smem: A 2 k-chunks x [128r x 128 fp8] XOR-swizzled = 32768
//       B 3 bufs x [128n x 128 fp8] swizzled = 49152
#define OFF_A   0
#define OFF_B   32768
#define OFF_RED 81920
#define SMEM_TOTAL 82944
#define NCH 32     // (NS/2)/128 n-tiles * 2 k-chunks
#define WSCALE 16.0f
#define INV_WSCALE 0.0625f

// ---------------- device scratch ----------------
__device__ __align__(16) uint8_t g_Bw8[NS * EMBED];  // gathered sampled weights, e4m3 (x16)
__device__ float g_c[NS];
__device__ float g_ps[2][BATCH];
__device__ float g_true[BATCH];

__device__ __forceinline__ float neg_log_ec(float fid) {
    const float inv_logv = 1.0f / logf((float)VOCAB + 1.0f);
    float p  = (logf(fid + 2.0f) - logf(fid + 1.0f)) * inv_logv;
    float ec = -expm1f((float)NS * log1pf(-p));
    return -logf(ec);
}

__device__ __forceinline__ unsigned su32(const void* p) {
    return (unsigned)__cvta_generic_to_shared(p);
}

__device__ __forceinline__ unsigned short f2_to_e4m3x2(float a, float b) {
    float2 v = make_float2(a, b);
    return (unsigned short)__nv_cvt_float2_to_fp8x2(v, __NV_SATFINITE, __NV_E4M3);
}

// convert 16 consecutive floats (as 4 float4) to 16 e4m3 bytes in a uint4
__device__ __forceinline__ uint4 cvt16(const float4* src, float scale) {
    __align__(16) unsigned short h[8];
    #pragma unroll
    for (int i = 0; i < 4; i++) {
        float4 v = src[i];
        h[i * 2 + 0] = f2_to_e4m3x2(v.x * scale, v.y * scale);
        h[i * 2 + 1] = f2_to_e4m3x2(v.z * scale, v.w * scale);
    }
    return *(const uint4*)h;
}

// ---------------- fused prep (gather B fp8, offsets c, true logits) ----------------
// blocks [0,256): gather+convert sampled weight rows to e4m3 (x16)
// blocks [256,272): c offsets
// blocks [272,784): true logits (fp32, 4 rows per warp)
__global__ void k_pre(const int* __restrict__ sids, const float* __restrict__ W,
                      const float* __restrict__ bias, const float* __restrict__ emb,
                      const int* __restrict__ tgt) {
    const int b   = blockIdx.x;
    const int tid = threadIdx.x;
    if (b < 256) {
        int i   = b * 256 + tid;          // NS*16 granules
        int s   = i >> 4;
        int g16 = (i & 15) * 16;
        int id  = sids[s];
        const float4* src = (const float4*)(W + (size_t)id * EMBED + g16);
        *(uint4*)(g_Bw8 + (size_t)s * EMBED + g16) = cvt16(src, WSCALE);
    } else if (b < 272) {
        int s  = (b - 256) * 256 + tid;
        int id = sids[s];
        g_c[s] = bias[id] + neg_log_ec((float)id);
    } else {
        const int tb   = b - 272;
        const int w    = tid >> 5;
        const int lane = tid & 31;
        const int r0   = (tb * 8 + w) * 4;
        int ids[4];
        #pragma unroll
        for (int j = 0; j < 4; j++) ids[j] = tgt[r0 + j];
        float s[4];
        #pragma unroll
        for (int j = 0; j < 4; j++) {
            const float4* e4 = (const float4*)(emb + (size_t)(r0 + j) * EMBED);
            const float4* w4 = (const float4*)(W + (size_t)ids[j] * EMBED);
            float4 a0 = e4[lane], a1 = e4[lane + 32];
            float4 b0 = w4[lane], b1 = w4[lane + 32];
            s[j] = a0.x*b0.x + a0.y*b0.y + a0.z*b0.z + a0.w*b0.w
                 + a1.x*b1.x + a1.y*b1.y + a1.z*b1.z + a1.w*b1.w;
        }
        #pragma unroll
        for (int off = 16; off > 0; off >>= 1)
            #pragma unroll
            for (int j = 0; j < 4; j++)
                s[j] += __shfl_xor_sync(0xffffffffu, s[j], off);
        if (lane == 0) {
            #pragma unroll
            for (int j = 0; j < 4; j++) {
                float tl = s[j] + bias[ids[j]] + neg_log_ec((float)ids[j]);
                g_true[r0 + j] = fmaxf(tl, 0.f) - tl + log1pf(expf(-fabsf(tl)));
            }
        }
    }
}

// ---------------- fused FP8 GEMM + softplus row-sum ----------------
// grid 256 = 128 M-tiles x 2 N-halves. 8 warps: 4M(32) x 2N(64). BN=128.
// mma.sync.m16n8k32 e4m3; XOR-swizzled smem; 3-stage B ring; A-frag dbuf.
__global__ __launch_bounds__(256, 2) void k_gemm(const float* __restrict__ emb) {
    extern __shared__ __align__(16) char smp[];
    const uint32_t base = su32(smp);
    float* red = (float*)(smp + OFF_RED);

    const int tid  = threadIdx.x;
    const int lane = tid & 31;
    const int warp = tid >> 5;
    const int wm   = warp & 3;   // 32-row group
    const int wn   = warp >> 2;  // 64-col group
    const int mb   = blockIdx.x >> 1;
    const int half = blockIdx.x & 1;
    const int m0   = mb * 128;
    const int nb0  = half * (NS / 2);

    // ---- B chunk loader: ch=(nt,kb) -> buf ch%3, 128n x 128 fp8 swizzled ----
    auto loadB = [&](int ch) {
        const int nt = ch >> 1, kb = ch & 1, b = ch % 3;
        const uint8_t* sb = g_Bw8 + (size_t)(nb0 + nt * 128) * EMBED + kb * 128;
        #pragma unroll
        for (int it = 0; it < 4; it++) {
            int q = tid + it * 256;           // 1024 granules of 16B
            int n = q >> 3, g = q & 7;
            uint32_t dst = base + OFF_B + b * 16384 + n * 128 + (((g ^ n) & 7) << 4);
            const void* src = sb + (size_t)n * EMBED + g * 16;
            asm volatile("cp.async.cg.shared.global [%0], [%1], 16;" :: "r"(dst), "l"(src));
        }
        asm volatile("cp.async.commit_group;");
    };

    loadB(0);
    loadB(1);

    // ---- A: load fp32 emb, convert to e4m3, swizzled store (2 k-chunks) ----
    #pragma unroll 4
    for (int it = 0; it < 8; it++) {
        int idx = tid + it * 256;             // 2048 granules of 16 fp8
        int r = idx >> 4, G = idx & 15;
        int c = G >> 3, g = G & 7;
        const float4* s = (const float4*)(emb + (size_t)(m0 + r) * EMBED + G * 16);
        *(uint4*)(smp + OFF_A + c * 16384 + r * 128 + (((g ^ r) & 7) << 4)) = cvt16(s, 1.0f);
    }

    float acc[2][8][4];
    #pragma unroll
    for (int mi = 0; mi < 2; mi++)
        #pragma unroll
        for (int ni = 0; ni < 8; ni++)
            #pragma unroll
            for (int q = 0; q < 4; q++) acc[mi][ni][q] = 0.0f;
    float rs[4] = {0.f, 0.f, 0.f, 0.f};

    // ---- fragment loaders (b16-unit view of fp8 pairs) ----
    auto ldA = [&](unsigned (&a)[2][4], uint32_t abase, int ki) {
        #pragma unroll
        for (int mi = 0; mi < 2; mi++) {
            int rr = wm * 32 + mi * 16 + (lane & 15);
            int gp = 2 * ki + (lane >> 4);
            unsigned addr = abase + rr * 128 + (((gp ^ rr) & 7) << 4);
            asm volatile("ldmatrix.sync.aligned.m8n8.x4.shared.b16 {%0,%1,%2,%3}, [%4];\n"
                : "=r"(a[mi][0]), "=r"(a[mi][1]), "=r"(a[mi][2]), "=r"(a[mi][3])
                : "r"(addr));
        }
    };
    auto ldBf = [&](unsigned (&b)[8][2], uint32_t bbase, int ki) {
        #pragma unroll
        for (int np = 0; np < 4; np++) {
            int nn = wn * 64 + np * 16 + ((lane >> 4) << 3) + (lane & 7);
            int gp = 2 * ki + ((lane >> 3) & 1);
            unsigned addr = bbase + nn * 128 + (((gp ^ nn) & 7) << 4);
            asm volatile("ldmatrix.sync.aligned.m8n8.x4.shared.b16 {%0,%1,%2,%3}, [%4];\n"
                : "=r"(b[np * 2][0]), "=r"(b[np * 2][1]),
                  "=r"(b[np * 2 + 1][0]), "=r"(b[np * 2 + 1][1])
                : "r"(addr));
        }
    };

    for (int ch = 0; ch < NCH; ch++) {
        if (ch < NCH - 1) asm volatile("cp.async.wait_group 1;");
        else              asm volatile("cp.async.wait_group 0;");
        __syncthreads();                       // chunk ch ready; buf (ch+2)%3 free
        if (ch + 2 < NCH) loadB(ch + 2);

        const int kb = ch & 1;
        const uint32_t abase = base + OFF_A + kb * 16384;
        const uint32_t bbase = base + OFF_B + (ch % 3) * 16384;

        unsigned aF[2][2][4];
        unsigned bF[8][2];
        ldA(aF[0], abase, 0);

        #pragma unroll
        for (int ki = 0; ki < 4; ki++) {
            ldBf(bF, bbase, ki);
            if (ki < 3) ldA(aF[(ki + 1) & 1], abase, ki + 1);
            unsigned (&a)[2][4] = aF[ki & 1];
            #pragma unroll
            for (int mi = 0; mi < 2; mi++)
                #pragma unroll
                for (int ni = 0; ni < 8; ni++)
                    asm volatile(
                        "mma.sync.aligned.m16n8k32.row.col.f32.e4m3.e4m3.f32 "
                        "{%0,%1,%2,%3},{%4,%5,%6,%7},{%8,%9},{%0,%1,%2,%3};\n"
                        : "+f"(acc[mi][ni][0]), "+f"(acc[mi][ni][1]),
                          "+f"(acc[mi][ni][2]), "+f"(acc[mi][ni][3])
                        : "r"(a[mi][0]), "r"(a[mi][1]), "r"(a[mi][2]), "r"(a[mi][3]),
                          "r"(bF[ni][0]), "r"(bF[ni][1]));
        }

        if (kb == 1) {
            const int nt = ch >> 1;
            const float* cp = g_c + nb0 + nt * 128 + wn * 64 + (lane & 3) * 2;
            #pragma unroll
            for (int mi = 0; mi < 2; mi++) {
                float lin0 = 0.f, lin1 = 0.f, pr0 = 1.f, pr1 = 1.f;
                #pragma unroll
                for (int ni = 0; ni < 8; ni++) {
                    float2 cf = *(const float2*)(cp + ni * 8);
                    float l0 = fmaf(acc[mi][ni][0], INV_WSCALE, cf.x);
                    float l1 = fmaf(acc[mi][ni][1], INV_WSCALE, cf.y);
                    float l2 = fmaf(acc[mi][ni][2], INV_WSCALE, cf.x);
                    float l3 = fmaf(acc[mi][ni][3], INV_WSCALE, cf.y);
                    lin0 += fmaxf(l0, 0.f) + fmaxf(l1, 0.f);
                    lin1 += fmaxf(l2, 0.f) + fmaxf(l3, 0.f);
                    pr0 *= (1.f + __expf(-fabsf(l0))) * (1.f + __expf(-fabsf(l1)));
                    pr1 *= (1.f + __expf(-fabsf(l2))) * (1.f + __expf(-fabsf(l3)));
                    acc[mi][ni][0] = 0.f; acc[mi][ni][1] = 0.f;
                    acc[mi][ni][2] = 0.f; acc[mi][ni][3] = 0.f;
                }
                rs[mi * 2 + 0] += lin0 + __logf(pr0);
                rs[mi * 2 + 1] += lin1 + __logf(pr1);
            }
        }
    }

    // ---- row-sum reduction ----
    #pragma unroll
    for (int s = 0; s < 4; s++) {
        rs[s] += __shfl_xor_sync(0xffffffffu, rs[s], 1);
        rs[s] += __shfl_xor_sync(0xffffffffu, rs[s], 2);
    }
    __syncthreads();
    if ((lane & 3) == 0) {
        #pragma unroll
        for (int s = 0; s < 4; s++) {
            int mi = s >> 1, hi = s & 1;
            int row = wm * 32 + mi * 16 + hi * 8 + (lane >> 2);
            red[wn * 128 + row] = rs[s];
        }
    }
    __syncthreads();
    if (tid < 128)
        g_ps[half][m0 + tid] = red[tid] + red[128 + tid];
}

// ---------------- final mean: 1024 threads, vectorized ----------------
__global__ void k_final(float* __restrict__ out) {
    __shared__ double redd[1024];
    const int tid = threadIdx.x;
    float s = 0.0f;
    const float4* p0 = (const float4*)g_ps[0];
    const float4* p1 = (const float4*)g_ps[1];
    const float4* p2 = (const float4*)g_true;
    #pragma unroll
    for (int i = 0; i < BATCH / 4 / 1024; i++) {
        int idx = tid + i * 1024;
        float4 a = p0[idx], b = p1[idx], c = p2[idx];
        s += a.x + a.y + a.z + a.w + b.x + b.y + b.z + b.w
           + c.x + c.y + c.z + c.w;
    }
    redd[tid] = (double)s;
    __syncthreads();
    for (int st = 512; st > 0; st >>= 1) {
        if (tid < st) redd[tid] += redd[tid + st];
        __syncthreads();
    }
    if (tid == 0) out[0] = (float)(redd[0] / (double)BATCH);
}

// ---------------- launch ----------------
extern "C" void kernel_launch(void* const* d_in, const int* in_sizes, int n_in,
                              void* d_out, int out_size) {
    const float* emb  = (const float*)d_in[0];
    const int*   tgt  = (const int*)d_in[1];
    const int*   sids = (const int*)d_in[2];
    const float* W    = (const float*)d_in[3];
    const float* bias = (const float*)d_in[4];
    float*       out  = (float*)d_out;

    cudaFuncSetAttribute(k_gemm, cudaFuncAttributeMaxDynamicSharedMemorySize, SMEM_TOTAL);

    k_pre<<<784, 256>>>(sids, W, bias, emb, tgt);
    k_gemm<<<256, 256, SMEM_TOTAL>>>(emb);
    k_final<<<1, 1024>>>(out);
}